// round 12
// baseline (speedup 1.0000x reference)
#include <cuda_runtime.h>
#include <math.h>

#define NLAYER 6
#define HEADS  12
#define DMODEL 384
#define DKH    32
#define DFF    1536
#define SEQ    512
#define BATCH  64
#define NTOK   (BATCH*SEQ)   /* 32768 */

typedef unsigned long long ull;

// ---------------- scratch (device globals; no allocs allowed) ----------------
__device__ float g_x[NTOK*DMODEL];
__device__ float g_q[NTOK*DMODEL];
__device__ float g_k[NTOK*DMODEL];
__device__ float g_v[NTOK*DMODEL];
__device__ float g_o[NTOK*DMODEL];
__device__ float g_t[NTOK*DMODEL];
__device__ float g_beta[NTOK*HEADS];
__device__ float g_h[NTOK*DFF];

// ---------------- helpers ----------------
__device__ __forceinline__ float warpSum(float v) {
#pragma unroll
    for (int o = 16; o > 0; o >>= 1) v += __shfl_xor_sync(0xffffffffu, v, o);
    return v;
}

__device__ __forceinline__ float gelu_t(float x) {
    float u = 0.7978845608028654f * (x + 0.044715f * x * x * x);
    return 0.5f * x * (1.0f + tanhf(u));
}

__device__ __forceinline__ float sigm(float x) {
    return 1.0f / (1.0f + expf(-x));
}

// ---- packed f32x2 (Blackwell FFMA2 — only reachable via PTX) ----
__device__ __forceinline__ ull pack2(float lo, float hi) {
    ull r; asm("mov.b64 %0, {%1, %2};" : "=l"(r) : "f"(lo), "f"(hi)); return r;
}
__device__ __forceinline__ void unpack2(ull v, float& lo, float& hi) {
    asm("mov.b64 {%0, %1}, %2;" : "=f"(lo), "=f"(hi) : "l"(v));
}
__device__ __forceinline__ ull fma2(ull a, ull b, ull c) {
    ull d; asm("fma.rn.f32x2 %0, %1, %2, %3;" : "=l"(d) : "l"(a), "l"(b), "l"(c)); return d;
}
__device__ __forceinline__ ull mul2(ull a, ull b) {
    ull d; asm("mul.rn.f32x2 %0, %1, %2;" : "=l"(d) : "l"(a), "l"(b)); return d;
}
__device__ __forceinline__ ull add2(ull a, ull b) {
    ull d; asm("add.rn.f32x2 %0, %1, %2;" : "=l"(d) : "l"(a), "l"(b)); return d;
}

__device__ __forceinline__ void mma_tf32u(float* d, const unsigned* a, const float* b) {
    asm volatile(
        "mma.sync.aligned.m16n8k8.row.col.f32.tf32.tf32.f32 "
        "{%0,%1,%2,%3}, {%4,%5,%6,%7}, {%8,%9}, {%0,%1,%2,%3};\n"
        : "+f"(d[0]), "+f"(d[1]), "+f"(d[2]), "+f"(d[3])
        : "r"(a[0]), "r"(a[1]), "r"(a[2]), "r"(a[3]),
          "r"(__float_as_uint(b[0])), "r"(__float_as_uint(b[1])));
}

__device__ __forceinline__ void ldsm_x4(unsigned* r, unsigned addr) {
    asm volatile("ldmatrix.sync.aligned.m8n8.x4.shared.b16 {%0,%1,%2,%3}, [%4];\n"
        : "=r"(r[0]), "=r"(r[1]), "=r"(r[2]), "=r"(r[3]) : "r"(addr));
}

__device__ __forceinline__ void cp_async16(unsigned smem_addr, const void* gptr) {
    asm volatile("cp.async.cg.shared.global [%0], [%1], 16;\n"
        :: "r"(smem_addr), "l"(gptr));
}

// ---------------- embedding + layernorm ----------------
__global__ void embed_ln_kernel(const int* __restrict__ ids,
                                const float* __restrict__ we,
                                const float* __restrict__ pe,
                                const float* __restrict__ te,
                                const float* __restrict__ g,
                                const float* __restrict__ bta) {
    int token = blockIdx.x;
    int l = token & (SEQ - 1);
    int id = ids[token];
    int tid = threadIdx.x;
    __shared__ float red[4];

    float v[3];
    float s = 0.f;
#pragma unroll
    for (int j = 0; j < 3; j++) {
        int d = tid + j * 128;
        float val = we[id * DMODEL + d] + pe[l * DMODEL + d] + te[d];
        v[j] = val; s += val;
    }
    s = warpSum(s);
    if ((tid & 31) == 0) red[tid >> 5] = s;
    __syncthreads();
    float mean = (red[0] + red[1] + red[2] + red[3]) * (1.0f / DMODEL);
    float s2 = 0.f;
#pragma unroll
    for (int j = 0; j < 3; j++) { float d0 = v[j] - mean; s2 += d0 * d0; }
    s2 = warpSum(s2);
    __syncthreads();
    if ((tid & 31) == 0) red[tid >> 5] = s2;
    __syncthreads();
    float var = (red[0] + red[1] + red[2] + red[3]) * (1.0f / DMODEL);
    float inv = rsqrtf(var + 1e-12f);
#pragma unroll
    for (int j = 0; j < 3; j++) {
        int d = tid + j * 128;
        g_x[token * DMODEL + d] = (v[j] - mean) * inv * g[d] + bta[d];
    }
}

// ---------------- residual add + layernorm (in-place on x) ----------------
__global__ void add_ln_kernel(float* __restrict__ x,
                              const float* __restrict__ t,
                              const float* __restrict__ g,
                              const float* __restrict__ bta) {
    int token = blockIdx.x;
    int tid = threadIdx.x;
    __shared__ float red[4];
    float v[3];
    float s = 0.f;
#pragma unroll
    for (int j = 0; j < 3; j++) {
        int d = tid + j * 128;
        float val = x[token * DMODEL + d] + t[token * DMODEL + d];
        v[j] = val; s += val;
    }
    s = warpSum(s);
    if ((tid & 31) == 0) red[tid >> 5] = s;
    __syncthreads();
    float mean = (red[0] + red[1] + red[2] + red[3]) * (1.0f / DMODEL);
    float s2 = 0.f;
#pragma unroll
    for (int j = 0; j < 3; j++) { float d0 = v[j] - mean; s2 += d0 * d0; }
    s2 = warpSum(s2);
    __syncthreads();
    if ((tid & 31) == 0) red[tid >> 5] = s2;
    __syncthreads();
    float var = (red[0] + red[1] + red[2] + red[3]) * (1.0f / DMODEL);
    float inv = rsqrtf(var + 1e-12f);
#pragma unroll
    for (int j = 0; j < 3; j++) {
        int d = tid + j * 128;
        x[token * DMODEL + d] = (v[j] - mean) * inv * g[d] + bta[d];
    }
}

// ---------------- TF32 tensor-core GEMM core (cp.async 4-stage, ldmatrix A) ----
#define GSTAGES 4
#define APITCH  20
#define BPITCH  136
#define GEMM_SMEM (GSTAGES * (128 * APITCH + 16 * BPITCH) * 4)

__device__ __forceinline__ void gemm_core(
        const float* __restrict__ A, const float* __restrict__ B,
        int bm, int bn, int N, int K, float* smem, float acc[4][4][4]) {
    const int BM = 128, BK = 16;
    float* As = smem;                           // [S][128][APITCH]
    float* Bs = smem + GSTAGES * BM * APITCH;   // [S][16][BPITCH]

    const int tid  = threadIdx.x;
    const int lane = tid & 31;
    const int wid  = tid >> 5;
    const int tig  = lane & 3;
    const int grp  = lane >> 2;
    const int wm   = (wid & 1) * 64;
    const int wn   = (wid >> 1) * 32;

    const int am0 = tid >> 2;
    const int am1 = (tid + 256) >> 2;
    const int ac0 = (tid & 3) * 4;
    const int bk0 = tid >> 5;
    const int bk1 = (tid + 256) >> 5;
    const int bn4 = (tid & 31) * 4;

    const unsigned aSh = (unsigned)__cvta_generic_to_shared(As);
    const unsigned bSh = (unsigned)__cvta_generic_to_shared(Bs);

    const int arow = lane & 15;
    const int aoff = (lane >> 4) << 2;

    const int nk = K / BK;

#define ISSUE_STAGE(KT, S)                                                        \
    do {                                                                          \
        int _k0 = (KT) * BK;                                                      \
        unsigned _ab = aSh + (unsigned)(S) * BM * APITCH * 4;                     \
        unsigned _bb = bSh + (unsigned)(S) * BK * BPITCH * 4;                     \
        cp_async16(_ab + (am0 * APITCH + ac0) * 4,                                \
                   A + (size_t)(bm + am0) * K + _k0 + ac0);                       \
        cp_async16(_ab + (am1 * APITCH + ac0) * 4,                                \
                   A + (size_t)(bm + am1) * K + _k0 + ac0);                       \
        cp_async16(_bb + (bk0 * BPITCH + bn4) * 4,                                \
                   B + (size_t)(_k0 + bk0) * N + bn + bn4);                       \
        cp_async16(_bb + (bk1 * BPITCH + bn4) * 4,                                \
                   B + (size_t)(_k0 + bk1) * N + bn + bn4);                       \
    } while (0)

#pragma unroll
    for (int s = 0; s < GSTAGES - 1; s++) {
        if (s < nk) ISSUE_STAGE(s, s);
        asm volatile("cp.async.commit_group;\n" ::);
    }

    for (int kt = 0; kt < nk; kt++) {
        asm volatile("cp.async.wait_group %0;\n" :: "n"(GSTAGES - 2));
        __syncthreads();

        int knext = kt + GSTAGES - 1;
        if (knext < nk) ISSUE_STAGE(knext, knext % GSTAGES);
        asm volatile("cp.async.commit_group;\n" ::);

        const unsigned aBase = aSh + (unsigned)(kt % GSTAGES) * BM * APITCH * 4;
        const float* Bsl = Bs + (kt % GSTAGES) * BK * BPITCH;
#pragma unroll
        for (int ks = 0; ks < 2; ks++) {
            unsigned a[4][4];
            float b[4][2];
#pragma unroll
            for (int im = 0; im < 4; im++)
                ldsm_x4(a[im], aBase +
                        (unsigned)(((wm + im * 16 + arow) * APITCH + 8 * ks + aoff) * 4));
#pragma unroll
            for (int in_ = 0; in_ < 4; in_++) {
                int n = wn + in_ * 8 + grp;
                b[in_][0] = Bsl[(ks * 8 + tig) * BPITCH + n];
                b[in_][1] = Bsl[(ks * 8 + tig + 4) * BPITCH + n];
            }
#pragma unroll
            for (int im = 0; im < 4; im++)
#pragma unroll
                for (int in_ = 0; in_ < 4; in_++)
                    mma_tf32u(acc[im][in_], a[im], b[in_]);
        }
    }
#undef ISSUE_STAGE
}

// ---------------- generic GEMM: C = A@B + bias (EPI=1: double-gelu) ----------
template<int EPI>
__global__ void __launch_bounds__(256, 2) tf32_gemm_async(
        const float* __restrict__ A, const float* __restrict__ B,
        const float* __restrict__ bias, float* __restrict__ C,
        int M, int N, int K) {
    extern __shared__ float smem[];
    const int tid  = threadIdx.x;
    const int lane = tid & 31;
    const int wid  = tid >> 5;
    const int tig  = lane & 3;
    const int grp  = lane >> 2;
    const int wm   = (wid & 1) * 64;
    const int wn   = (wid >> 1) * 32;
    const int bm   = blockIdx.y * 128;
    const int bn   = blockIdx.x * 128;

    float acc[4][4][4];
#pragma unroll
    for (int im = 0; im < 4; im++)
#pragma unroll
        for (int in_ = 0; in_ < 4; in_++)
#pragma unroll
            for (int r = 0; r < 4; r++) acc[im][in_][r] = 0.f;

    gemm_core(A, B, bm, bn, N, K, smem, acc);

#pragma unroll
    for (int im = 0; im < 4; im++) {
        int row0 = bm + wm + im * 16 + grp;
#pragma unroll
        for (int in_ = 0; in_ < 4; in_++) {
            int col = bn + wn + in_ * 8 + 2 * tig;
            float b0 = bias[col], b1 = bias[col + 1];
            float v0 = acc[im][in_][0] + b0;
            float v1 = acc[im][in_][1] + b1;
            float v2 = acc[im][in_][2] + b0;
            float v3 = acc[im][in_][3] + b1;
            if (EPI == 1) {
                v0 = gelu_t(gelu_t(v0)); v1 = gelu_t(gelu_t(v1));
                v2 = gelu_t(gelu_t(v2)); v3 = gelu_t(gelu_t(v3));
            }
            *(float2*)&C[(size_t)row0 * N + col]       = make_float2(v0, v1);
            *(float2*)&C[(size_t)(row0 + 8) * N + col] = make_float2(v2, v3);
        }
    }
}

// ---------------- fused QKV GEMM with per-head l2-norm epilogue --------------
__global__ void __launch_bounds__(256, 2) tf32_gemm_qkv(
        const float* __restrict__ A,
        const float* __restrict__ BQ, const float* __restrict__ BK_,
        const float* __restrict__ BV,
        const float* __restrict__ bqv, const float* __restrict__ bkv,
        const float* __restrict__ bvv,
        float* __restrict__ CQ, float* __restrict__ CK, float* __restrict__ CV,
        const float* __restrict__ mask, int M, int N, int K) {
    extern __shared__ float smem[];
    const int z = blockIdx.z;
    const float* B    = (z == 0) ? BQ  : (z == 1) ? BK_ : BV;
    const float* bias = (z == 0) ? bqv : (z == 1) ? bkv : bvv;
    float* C          = (z == 0) ? CQ  : (z == 1) ? CK  : CV;

    const int tid  = threadIdx.x;
    const int lane = tid & 31;
    const int wid  = tid >> 5;
    const int tig  = lane & 3;
    const int grp  = lane >> 2;
    const int wm   = (wid & 1) * 64;
    const int wn   = (wid >> 1) * 32;
    const int bm   = blockIdx.y * 128;
    const int bn   = blockIdx.x * 128;

    float acc[4][4][4];
#pragma unroll
    for (int im = 0; im < 4; im++)
#pragma unroll
        for (int in_ = 0; in_ < 4; in_++)
#pragma unroll
            for (int r = 0; r < 4; r++) acc[im][in_][r] = 0.f;

    gemm_core(A, B, bm, bn, N, K, smem, acc);

#pragma unroll
    for (int im = 0; im < 4; im++) {
        int row0 = bm + wm + im * 16 + grp;
#pragma unroll
        for (int in_ = 0; in_ < 4; in_++) {
            int col = bn + wn + in_ * 8 + 2 * tig;
            float b0 = bias[col], b1 = bias[col + 1];
            acc[im][in_][0] += b0; acc[im][in_][1] += b1;
            acc[im][in_][2] += b0; acc[im][in_][3] += b1;
        }
        float sA = 1.f, sB = 1.f;
        if (z < 2) {
            float ssA = 0.f, ssB = 0.f;
#pragma unroll
            for (int in_ = 0; in_ < 4; in_++) {
                ssA += acc[im][in_][0] * acc[im][in_][0]
                     + acc[im][in_][1] * acc[im][in_][1];
                ssB += acc[im][in_][2] * acc[im][in_][2]
                     + acc[im][in_][3] * acc[im][in_][3];
            }
            ssA += __shfl_xor_sync(0xffffffffu, ssA, 1);
            ssA += __shfl_xor_sync(0xffffffffu, ssA, 2);
            ssB += __shfl_xor_sync(0xffffffffu, ssB, 1);
            ssB += __shfl_xor_sync(0xffffffffu, ssB, 2);
            sA = 1.0f / (sqrtf(ssA) + 1e-6f);
            sB = 1.0f / (sqrtf(ssB) + 1e-6f);
            if (z == 1) {
                sA *= mask[row0];
                sB *= mask[row0 + 8];
            }
        }
#pragma unroll
        for (int in_ = 0; in_ < 4; in_++) {
            int col = bn + wn + in_ * 8 + 2 * tig;
            *(float2*)&C[(size_t)row0 * N + col] =
                make_float2(acc[im][in_][0] * sA, acc[im][in_][1] * sA);
            *(float2*)&C[(size_t)(row0 + 8) * N + col] =
                make_float2(acc[im][in_][2] * sB, acc[im][in_][3] * sB);
        }
    }
}

// ---------------- beta = sigmoid(x @ Wb) * mask ----------------
__global__ void beta_kernel(const float* __restrict__ x, const float* __restrict__ Wb,
                            const float* __restrict__ mask) {
    int token = blockIdx.x;
    int h = threadIdx.x >> 5;
    int lane = threadIdx.x & 31;
    const float* xr = x + (size_t)token * DMODEL;
    float s = 0.f;
#pragma unroll
    for (int k = lane; k < DMODEL; k += 32) s += xr[k] * Wb[k * HEADS + h];
    s = warpSum(s);
    if (lane == 0) g_beta[token * HEADS + h] = sigm(s) * mask[token];
}

// ---------------- delta recurrence: TWO warps per (b,h) — one per state -----
// warp0 owns the fast state, warp1 the slow state; each runs half the per-step
// instruction stream in packed f32x2. warp0 broadcasts k/q via smem (bar#1);
// warp1 publishes its partial output (bar#2); warp0 combines and stores.
__global__ void __launch_bounds__(64) delta_kernel(
        const float* __restrict__ decay_f,
        const float* __restrict__ decay_s,
        int layer) {
    int bh = blockIdx.x;
    int b = bh / HEADS;
    int h = bh % HEADS;
    int wid  = threadIdx.x >> 5;   // 0 = fast, 1 = slow
    int lane = threadIdx.x & 31;

    float g = sigm((wid == 0 ? decay_f : decay_s)[layer * HEADS + h]);
    const ull g2 = pack2(g, g);

    ull S[16];
#pragma unroll
    for (int j = 0; j < 16; j++) S[j] = 0ull;

    __shared__ float ks[DKH], qs[DKH], osm[DKH];

    const size_t base = (size_t)(b * SEQ) * DMODEL + h * DKH + lane;
    const int bbase = b * SEQ * HEADS + h;

    // 2-deep prefetch pipeline: q/k only needed by warp0 (smem producer),
    // v/beta by both.
    float q0 = 0.f, k0 = 0.f, q1 = 0.f, k1 = 0.f;
    if (wid == 0) {
        q0 = g_q[base]; k0 = g_k[base];
        q1 = g_q[base + DMODEL]; k1 = g_k[base + DMODEL];
    }
    float v0 = g_v[base], b0 = g_beta[bbase];
    float v1 = g_v[base + DMODEL], b1 = g_beta[bbase + HEADS];

    for (int t = 0; t < SEQ; t++) {
        float qN = 0.f, kN = 0.f, vN = 0.f, bN = 0.f;
        if (t + 2 < SEQ) {
            size_t idn = base + (size_t)(t + 2) * DMODEL;
            if (wid == 0) { qN = g_q[idn]; kN = g_k[idn]; }
            vN = g_v[idn];
            bN = g_beta[bbase + (t + 2) * HEADS];
        }

        if (wid == 0) { ks[lane] = k0; qs[lane] = q0; }
        __syncthreads();   // bar#1: k/q broadcast visible

        // p = k . S  (packed dot over k-dim, 2 accumulators)
        ull k2[16];
        ull p0 = 0ull, p1 = 0ull;
#pragma unroll
        for (int j = 0; j < 16; j += 2) {
            k2[j]     = *(const ull*)&ks[2 * j];
            k2[j + 1] = *(const ull*)&ks[2 * j + 2];
            p0 = fma2(k2[j],     S[j],     p0);
            p1 = fma2(k2[j + 1], S[j + 1], p1);
        }
        float pa, pb;
        unpack2(add2(p0, p1), pa, pb);
        float p = pa + pb;

        float c = b0 * (v0 - p);
        const ull c2 = pack2(c, c);

        // state update + output accumulation
        ull o0 = 0ull, o1 = 0ull;
#pragma unroll
        for (int j = 0; j < 16; j += 2) {
            ull q2a = *(const ull*)&qs[2 * j];
            ull q2b = *(const ull*)&qs[2 * j + 2];
            S[j]     = fma2(g2, S[j],     mul2(k2[j],     c2));
            S[j + 1] = fma2(g2, S[j + 1], mul2(k2[j + 1], c2));
            o0 = fma2(q2a, S[j],     o0);
            o1 = fma2(q2b, S[j + 1], o1);
        }
        float oa, ob;
        unpack2(add2(o0, o1), oa, ob);
        float o = oa + ob;

        if (wid == 1) osm[lane] = o;
        __syncthreads();   // bar#2: slow partial visible
        if (wid == 0)
            g_o[base + (size_t)t * DMODEL] = 0.5f * (o + osm[lane]);

        q0 = q1; k0 = k1; v0 = v1; b0 = b1;
        q1 = qN; k1 = kN; v1 = vN; b1 = bN;
    }
}

// ---------------- masked mean pool + l2 normalize ----------------
__global__ void pool_kernel(const float* __restrict__ mask, float* __restrict__ out) {
    int b = blockIdx.x;
    int d = threadIdx.x;        // 384 threads
    __shared__ float red[12];

    float s = 0.f, msum = 0.f;
    for (int l = 0; l < SEQ; l++) {
        float mv = mask[b * SEQ + l];
        s += g_x[(size_t)(b * SEQ + l) * DMODEL + d] * mv;
        msum += mv;
    }
    float emb = s / fmaxf(msum, 1e-9f);

    float ss = warpSum(emb * emb);
    if ((d & 31) == 0) red[d >> 5] = ss;
    __syncthreads();
    float tot = 0.f;
#pragma unroll
    for (int w = 0; w < 12; w++) tot += red[w];
    float n = fmaxf(sqrtf(tot), 1e-12f);
    out[b * DMODEL + d] = emb / n;
}

// ---------------- launch ----------------
extern "C" void kernel_launch(void* const* d_in, const int* in_sizes, int n_in,
                              void* d_out, int out_size) {
    const int*   input_ids = (const int*)  d_in[0];
    const float* attn_mask = (const float*)d_in[1];
    const float* word_emb  = (const float*)d_in[2];
    const float* pos_emb   = (const float*)d_in[3];
    const float* type_emb  = (const float*)d_in[4];
    const float* emb_ln_g  = (const float*)d_in[5];
    const float* emb_ln_b  = (const float*)d_in[6];
    const float* Wq  = (const float*)d_in[7];
    const float* bq  = (const float*)d_in[8];
    const float* Wk  = (const float*)d_in[9];
    const float* bk  = (const float*)d_in[10];
    const float* Wv  = (const float*)d_in[11];
    const float* bv  = (const float*)d_in[12];
    const float* Wb  = (const float*)d_in[13];
    const float* dfa = (const float*)d_in[14];
    const float* dsl = (const float*)d_in[15];
    const float* Wo  = (const float*)d_in[16];
    const float* bo  = (const float*)d_in[17];
    const float* ln1g = (const float*)d_in[18];
    const float* ln1b = (const float*)d_in[19];
    const float* W1  = (const float*)d_in[20];
    const float* b1  = (const float*)d_in[21];
    const float* W2  = (const float*)d_in[22];
    const float* b2  = (const float*)d_in[23];
    const float* ln2g = (const float*)d_in[24];
    const float* ln2b = (const float*)d_in[25];
    float* out = (float*)d_out;

    float *px, *pq, *pk, *pv, *po, *pt, *ph;
    cudaGetSymbolAddress((void**)&px, g_x);
    cudaGetSymbolAddress((void**)&pq, g_q);
    cudaGetSymbolAddress((void**)&pk, g_k);
    cudaGetSymbolAddress((void**)&pv, g_v);
    cudaGetSymbolAddress((void**)&po, g_o);
    cudaGetSymbolAddress((void**)&pt, g_t);
    cudaGetSymbolAddress((void**)&ph, g_h);

    cudaFuncSetAttribute(tf32_gemm_async<0>,
                         cudaFuncAttributeMaxDynamicSharedMemorySize, GEMM_SMEM);
    cudaFuncSetAttribute(tf32_gemm_async<1>,
                         cudaFuncAttributeMaxDynamicSharedMemorySize, GEMM_SMEM);
    cudaFuncSetAttribute(tf32_gemm_qkv,
                         cudaFuncAttributeMaxDynamicSharedMemorySize, GEMM_SMEM);

    embed_ln_kernel<<<NTOK, 128>>>(input_ids, word_emb, pos_emb, type_emb, emb_ln_g, emb_ln_b);

    dim3 gProj(DMODEL / 128, NTOK / 128);       // (3,256)
    dim3 gQKV(DMODEL / 128, NTOK / 128, 3);     // (3,256,3)
    dim3 gFF1(DFF / 128, NTOK / 128);           // (12,256)

    for (int i = 0; i < NLAYER; i++) {
        const float* Wqi = Wq + (size_t)i * DMODEL * DMODEL;
        const float* Wki = Wk + (size_t)i * DMODEL * DMODEL;
        const float* Wvi = Wv + (size_t)i * DMODEL * DMODEL;
        const float* Woi = Wo + (size_t)i * DMODEL * DMODEL;
        const float* W1i = W1 + (size_t)i * DMODEL * DFF;
        const float* W2i = W2 + (size_t)i * DFF * DMODEL;

        tf32_gemm_qkv<<<gQKV, 256, GEMM_SMEM>>>(
            px, Wqi, Wki, Wvi,
            bq + i * DMODEL, bk + i * DMODEL, bv + i * DMODEL,
            pq, pk, pv, attn_mask, NTOK, DMODEL, DMODEL);
        beta_kernel<<<NTOK, 384>>>(px, Wb + (size_t)i * DMODEL * HEADS, attn_mask);

        delta_kernel<<<BATCH * HEADS, 64>>>(dfa, dsl, i);

        tf32_gemm_async<0><<<gProj, 256, GEMM_SMEM>>>(po, Woi, bo + i * DMODEL, pt, NTOK, DMODEL, DMODEL);
        add_ln_kernel<<<NTOK, 128>>>(px, pt, ln1g + i * DMODEL, ln1b + i * DMODEL);

        tf32_gemm_async<1><<<gFF1, 256, GEMM_SMEM>>>(px, W1i, b1 + i * DFF, ph, NTOK, DFF, DMODEL);
        tf32_gemm_async<0><<<gProj, 256, GEMM_SMEM>>>(ph, W2i, b2 + i * DMODEL, pt, NTOK, DMODEL, DFF);
        add_ln_kernel<<<NTOK, 128>>>(px, pt, ln2g + i * DMODEL, ln2b + i * DMODEL);
    }

    pool_kernel<<<BATCH, 384>>>(attn_mask, out);
}

// round 13
// speedup vs baseline: 1.0348x; 1.0348x over previous
#include <cuda_runtime.h>
#include <math.h>

#define NLAYER 6
#define HEADS  12
#define DMODEL 384
#define DKH    32
#define DFF    1536
#define SEQ    512
#define BATCH  64
#define NTOK   (BATCH*SEQ)   /* 32768 */

typedef unsigned long long ull;

// ---------------- scratch (device globals; no allocs allowed) ----------------
__device__ float g_x[NTOK*DMODEL];
__device__ float g_q[NTOK*DMODEL];
__device__ float g_k[NTOK*DMODEL];
__device__ float g_v[NTOK*DMODEL];
__device__ float g_o[NTOK*DMODEL];
__device__ float g_t[NTOK*DMODEL];
__device__ float g_beta[NTOK*HEADS];
__device__ float g_h[NTOK*DFF];

// ---------------- helpers ----------------
__device__ __forceinline__ float warpSum(float v) {
#pragma unroll
    for (int o = 16; o > 0; o >>= 1) v += __shfl_xor_sync(0xffffffffu, v, o);
    return v;
}

__device__ __forceinline__ float gelu_t(float x) {
    float u = 0.7978845608028654f * (x + 0.044715f * x * x * x);
    return 0.5f * x * (1.0f + tanhf(u));
}

__device__ __forceinline__ float sigm(float x) {
    return 1.0f / (1.0f + expf(-x));
}

// ---- packed f32x2 (Blackwell FFMA2 — only reachable via PTX) ----
__device__ __forceinline__ ull pack2(float lo, float hi) {
    ull r; asm("mov.b64 %0, {%1, %2};" : "=l"(r) : "f"(lo), "f"(hi)); return r;
}
__device__ __forceinline__ void unpack2(ull v, float& lo, float& hi) {
    asm("mov.b64 {%0, %1}, %2;" : "=f"(lo), "=f"(hi) : "l"(v));
}
__device__ __forceinline__ ull fma2(ull a, ull b, ull c) {
    ull d; asm("fma.rn.f32x2 %0, %1, %2, %3;" : "=l"(d) : "l"(a), "l"(b), "l"(c)); return d;
}
__device__ __forceinline__ ull mul2(ull a, ull b) {
    ull d; asm("mul.rn.f32x2 %0, %1, %2;" : "=l"(d) : "l"(a), "l"(b)); return d;
}
__device__ __forceinline__ ull add2(ull a, ull b) {
    ull d; asm("add.rn.f32x2 %0, %1, %2;" : "=l"(d) : "l"(a), "l"(b)); return d;
}

__device__ __forceinline__ void mma_tf32u(float* d, const unsigned* a, const float* b) {
    asm volatile(
        "mma.sync.aligned.m16n8k8.row.col.f32.tf32.tf32.f32 "
        "{%0,%1,%2,%3}, {%4,%5,%6,%7}, {%8,%9}, {%0,%1,%2,%3};\n"
        : "+f"(d[0]), "+f"(d[1]), "+f"(d[2]), "+f"(d[3])
        : "r"(a[0]), "r"(a[1]), "r"(a[2]), "r"(a[3]),
          "r"(__float_as_uint(b[0])), "r"(__float_as_uint(b[1])));
}

__device__ __forceinline__ void ldsm_x4(unsigned* r, unsigned addr) {
    asm volatile("ldmatrix.sync.aligned.m8n8.x4.shared.b16 {%0,%1,%2,%3}, [%4];\n"
        : "=r"(r[0]), "=r"(r[1]), "=r"(r[2]), "=r"(r[3]) : "r"(addr));
}

__device__ __forceinline__ void cp_async16(unsigned smem_addr, const void* gptr) {
    asm volatile("cp.async.cg.shared.global [%0], [%1], 16;\n"
        :: "r"(smem_addr), "l"(gptr));
}

// ---------------- embedding + layernorm ----------------
__global__ void embed_ln_kernel(const int* __restrict__ ids,
                                const float* __restrict__ we,
                                const float* __restrict__ pe,
                                const float* __restrict__ te,
                                const float* __restrict__ g,
                                const float* __restrict__ bta) {
    int token = blockIdx.x;
    int l = token & (SEQ - 1);
    int id = ids[token];
    int tid = threadIdx.x;
    __shared__ float red[4];

    float v[3];
    float s = 0.f;
#pragma unroll
    for (int j = 0; j < 3; j++) {
        int d = tid + j * 128;
        float val = we[id * DMODEL + d] + pe[l * DMODEL + d] + te[d];
        v[j] = val; s += val;
    }
    s = warpSum(s);
    if ((tid & 31) == 0) red[tid >> 5] = s;
    __syncthreads();
    float mean = (red[0] + red[1] + red[2] + red[3]) * (1.0f / DMODEL);
    float s2 = 0.f;
#pragma unroll
    for (int j = 0; j < 3; j++) { float d0 = v[j] - mean; s2 += d0 * d0; }
    s2 = warpSum(s2);
    __syncthreads();
    if ((tid & 31) == 0) red[tid >> 5] = s2;
    __syncthreads();
    float var = (red[0] + red[1] + red[2] + red[3]) * (1.0f / DMODEL);
    float inv = rsqrtf(var + 1e-12f);
#pragma unroll
    for (int j = 0; j < 3; j++) {
        int d = tid + j * 128;
        g_x[token * DMODEL + d] = (v[j] - mean) * inv * g[d] + bta[d];
    }
}

// ---------------- residual add + layernorm (in-place on x) ----------------
__global__ void add_ln_kernel(float* __restrict__ x,
                              const float* __restrict__ t,
                              const float* __restrict__ g,
                              const float* __restrict__ bta) {
    int token = blockIdx.x;
    int tid = threadIdx.x;
    __shared__ float red[4];
    float v[3];
    float s = 0.f;
#pragma unroll
    for (int j = 0; j < 3; j++) {
        int d = tid + j * 128;
        float val = x[token * DMODEL + d] + t[token * DMODEL + d];
        v[j] = val; s += val;
    }
    s = warpSum(s);
    if ((tid & 31) == 0) red[tid >> 5] = s;
    __syncthreads();
    float mean = (red[0] + red[1] + red[2] + red[3]) * (1.0f / DMODEL);
    float s2 = 0.f;
#pragma unroll
    for (int j = 0; j < 3; j++) { float d0 = v[j] - mean; s2 += d0 * d0; }
    s2 = warpSum(s2);
    __syncthreads();
    if ((tid & 31) == 0) red[tid >> 5] = s2;
    __syncthreads();
    float var = (red[0] + red[1] + red[2] + red[3]) * (1.0f / DMODEL);
    float inv = rsqrtf(var + 1e-12f);
#pragma unroll
    for (int j = 0; j < 3; j++) {
        int d = tid + j * 128;
        x[token * DMODEL + d] = (v[j] - mean) * inv * g[d] + bta[d];
    }
}

// ---------------- TF32 tensor-core GEMM core (cp.async 4-stage, ldmatrix A) ----
#define GSTAGES 4
#define APITCH  20
#define BPITCH  136
#define GEMM_SMEM (GSTAGES * (128 * APITCH + 16 * BPITCH) * 4)

__device__ __forceinline__ void gemm_core(
        const float* __restrict__ A, const float* __restrict__ B,
        int bm, int bn, int N, int K, float* smem, float acc[4][4][4]) {
    const int BM = 128, BK = 16;
    float* As = smem;                           // [S][128][APITCH]
    float* Bs = smem + GSTAGES * BM * APITCH;   // [S][16][BPITCH]

    const int tid  = threadIdx.x;
    const int lane = tid & 31;
    const int wid  = tid >> 5;
    const int tig  = lane & 3;
    const int grp  = lane >> 2;
    const int wm   = (wid & 1) * 64;
    const int wn   = (wid >> 1) * 32;

    const int am0 = tid >> 2;
    const int am1 = (tid + 256) >> 2;
    const int ac0 = (tid & 3) * 4;
    const int bk0 = tid >> 5;
    const int bk1 = (tid + 256) >> 5;
    const int bn4 = (tid & 31) * 4;

    const unsigned aSh = (unsigned)__cvta_generic_to_shared(As);
    const unsigned bSh = (unsigned)__cvta_generic_to_shared(Bs);

    const int arow = lane & 15;
    const int aoff = (lane >> 4) << 2;

    const int nk = K / BK;

#define ISSUE_STAGE(KT, S)                                                        \
    do {                                                                          \
        int _k0 = (KT) * BK;                                                      \
        unsigned _ab = aSh + (unsigned)(S) * BM * APITCH * 4;                     \
        unsigned _bb = bSh + (unsigned)(S) * BK * BPITCH * 4;                     \
        cp_async16(_ab + (am0 * APITCH + ac0) * 4,                                \
                   A + (size_t)(bm + am0) * K + _k0 + ac0);                       \
        cp_async16(_ab + (am1 * APITCH + ac0) * 4,                                \
                   A + (size_t)(bm + am1) * K + _k0 + ac0);                       \
        cp_async16(_bb + (bk0 * BPITCH + bn4) * 4,                                \
                   B + (size_t)(_k0 + bk0) * N + bn + bn4);                       \
        cp_async16(_bb + (bk1 * BPITCH + bn4) * 4,                                \
                   B + (size_t)(_k0 + bk1) * N + bn + bn4);                       \
    } while (0)

#pragma unroll
    for (int s = 0; s < GSTAGES - 1; s++) {
        if (s < nk) ISSUE_STAGE(s, s);
        asm volatile("cp.async.commit_group;\n" ::);
    }

    for (int kt = 0; kt < nk; kt++) {
        asm volatile("cp.async.wait_group %0;\n" :: "n"(GSTAGES - 2));
        __syncthreads();

        int knext = kt + GSTAGES - 1;
        if (knext < nk) ISSUE_STAGE(knext, knext % GSTAGES);
        asm volatile("cp.async.commit_group;\n" ::);

        const unsigned aBase = aSh + (unsigned)(kt % GSTAGES) * BM * APITCH * 4;
        const float* Bsl = Bs + (kt % GSTAGES) * BK * BPITCH;
#pragma unroll
        for (int ks = 0; ks < 2; ks++) {
            unsigned a[4][4];
            float b[4][2];
#pragma unroll
            for (int im = 0; im < 4; im++)
                ldsm_x4(a[im], aBase +
                        (unsigned)(((wm + im * 16 + arow) * APITCH + 8 * ks + aoff) * 4));
#pragma unroll
            for (int in_ = 0; in_ < 4; in_++) {
                int n = wn + in_ * 8 + grp;
                b[in_][0] = Bsl[(ks * 8 + tig) * BPITCH + n];
                b[in_][1] = Bsl[(ks * 8 + tig + 4) * BPITCH + n];
            }
#pragma unroll
            for (int im = 0; im < 4; im++)
#pragma unroll
                for (int in_ = 0; in_ < 4; in_++)
                    mma_tf32u(acc[im][in_], a[im], b[in_]);
        }
    }
#undef ISSUE_STAGE
}

// ---------------- generic GEMM: C = A@B + bias (EPI=1: double-gelu) ----------
template<int EPI>
__global__ void __launch_bounds__(256, 2) tf32_gemm_async(
        const float* __restrict__ A, const float* __restrict__ B,
        const float* __restrict__ bias, float* __restrict__ C,
        int M, int N, int K) {
    extern __shared__ float smem[];
    const int tid  = threadIdx.x;
    const int lane = tid & 31;
    const int wid  = tid >> 5;
    const int tig  = lane & 3;
    const int grp  = lane >> 2;
    const int wm   = (wid & 1) * 64;
    const int wn   = (wid >> 1) * 32;
    const int bm   = blockIdx.y * 128;
    const int bn   = blockIdx.x * 128;

    float acc[4][4][4];
#pragma unroll
    for (int im = 0; im < 4; im++)
#pragma unroll
        for (int in_ = 0; in_ < 4; in_++)
#pragma unroll
            for (int r = 0; r < 4; r++) acc[im][in_][r] = 0.f;

    gemm_core(A, B, bm, bn, N, K, smem, acc);

#pragma unroll
    for (int im = 0; im < 4; im++) {
        int row0 = bm + wm + im * 16 + grp;
#pragma unroll
        for (int in_ = 0; in_ < 4; in_++) {
            int col = bn + wn + in_ * 8 + 2 * tig;
            float b0 = bias[col], b1 = bias[col + 1];
            float v0 = acc[im][in_][0] + b0;
            float v1 = acc[im][in_][1] + b1;
            float v2 = acc[im][in_][2] + b0;
            float v3 = acc[im][in_][3] + b1;
            if (EPI == 1) {
                v0 = gelu_t(gelu_t(v0)); v1 = gelu_t(gelu_t(v1));
                v2 = gelu_t(gelu_t(v2)); v3 = gelu_t(gelu_t(v3));
            }
            *(float2*)&C[(size_t)row0 * N + col]       = make_float2(v0, v1);
            *(float2*)&C[(size_t)(row0 + 8) * N + col] = make_float2(v2, v3);
        }
    }
}

// ---------------- fused QKV GEMM with per-head l2-norm epilogue --------------
__global__ void __launch_bounds__(256, 2) tf32_gemm_qkv(
        const float* __restrict__ A,
        const float* __restrict__ BQ, const float* __restrict__ BK_,
        const float* __restrict__ BV,
        const float* __restrict__ bqv, const float* __restrict__ bkv,
        const float* __restrict__ bvv,
        float* __restrict__ CQ, float* __restrict__ CK, float* __restrict__ CV,
        const float* __restrict__ mask, int M, int N, int K) {
    extern __shared__ float smem[];
    const int z = blockIdx.z;
    const float* B    = (z == 0) ? BQ  : (z == 1) ? BK_ : BV;
    const float* bias = (z == 0) ? bqv : (z == 1) ? bkv : bvv;
    float* C          = (z == 0) ? CQ  : (z == 1) ? CK  : CV;

    const int tid  = threadIdx.x;
    const int lane = tid & 31;
    const int wid  = tid >> 5;
    const int tig  = lane & 3;
    const int grp  = lane >> 2;
    const int wm   = (wid & 1) * 64;
    const int wn   = (wid >> 1) * 32;
    const int bm   = blockIdx.y * 128;
    const int bn   = blockIdx.x * 128;

    float acc[4][4][4];
#pragma unroll
    for (int im = 0; im < 4; im++)
#pragma unroll
        for (int in_ = 0; in_ < 4; in_++)
#pragma unroll
            for (int r = 0; r < 4; r++) acc[im][in_][r] = 0.f;

    gemm_core(A, B, bm, bn, N, K, smem, acc);

#pragma unroll
    for (int im = 0; im < 4; im++) {
        int row0 = bm + wm + im * 16 + grp;
#pragma unroll
        for (int in_ = 0; in_ < 4; in_++) {
            int col = bn + wn + in_ * 8 + 2 * tig;
            float b0 = bias[col], b1 = bias[col + 1];
            acc[im][in_][0] += b0; acc[im][in_][1] += b1;
            acc[im][in_][2] += b0; acc[im][in_][3] += b1;
        }
        float sA = 1.f, sB = 1.f;
        if (z < 2) {
            float ssA = 0.f, ssB = 0.f;
#pragma unroll
            for (int in_ = 0; in_ < 4; in_++) {
                ssA += acc[im][in_][0] * acc[im][in_][0]
                     + acc[im][in_][1] * acc[im][in_][1];
                ssB += acc[im][in_][2] * acc[im][in_][2]
                     + acc[im][in_][3] * acc[im][in_][3];
            }
            ssA += __shfl_xor_sync(0xffffffffu, ssA, 1);
            ssA += __shfl_xor_sync(0xffffffffu, ssA, 2);
            ssB += __shfl_xor_sync(0xffffffffu, ssB, 1);
            ssB += __shfl_xor_sync(0xffffffffu, ssB, 2);
            sA = 1.0f / (sqrtf(ssA) + 1e-6f);
            sB = 1.0f / (sqrtf(ssB) + 1e-6f);
            if (z == 1) {
                sA *= mask[row0];
                sB *= mask[row0 + 8];
            }
        }
#pragma unroll
        for (int in_ = 0; in_ < 4; in_++) {
            int col = bn + wn + in_ * 8 + 2 * tig;
            *(float2*)&C[(size_t)row0 * N + col] =
                make_float2(acc[im][in_][0] * sA, acc[im][in_][1] * sA);
            *(float2*)&C[(size_t)(row0 + 8) * N + col] =
                make_float2(acc[im][in_][2] * sB, acc[im][in_][3] * sB);
        }
    }
}

// ---------------- beta = sigmoid(x @ Wb) * mask ----------------
__global__ void beta_kernel(const float* __restrict__ x, const float* __restrict__ Wb,
                            const float* __restrict__ mask) {
    int token = blockIdx.x;
    int h = threadIdx.x >> 5;
    int lane = threadIdx.x & 31;
    const float* xr = x + (size_t)token * DMODEL;
    float s = 0.f;
#pragma unroll
    for (int k = lane; k < DMODEL; k += 32) s += xr[k] * Wb[k * HEADS + h];
    s = warpSum(s);
    if (lane == 0) g_beta[token * HEADS + h] = sigm(s) * mask[token];
}

// ---------------- delta recurrence: one warp per (b,h), f32x2 math,
//                  chunked cp.async SMEM staging (double-buffered) ----------
#define TCH 32   /* timesteps per chunk; SEQ/TCH = 16 chunks */

__global__ void __launch_bounds__(32) delta_kernel(
        const float* __restrict__ decay_f,
        const float* __restrict__ decay_s,
        int layer) {
    int bh = blockIdx.x;
    int b = bh / HEADS;
    int h = bh % HEADS;
    int lane = threadIdx.x;

    float gf = sigm(decay_f[layer * HEADS + h]);
    float gs = sigm(decay_s[layer * HEADS + h]);
    const ull gf2 = pack2(gf, gf);
    const ull gs2 = pack2(gs, gs);

    ull Sf[16], Ss[16];
#pragma unroll
    for (int j = 0; j < 16; j++) { Sf[j] = 0ull; Ss[j] = 0ull; }

    __shared__ float sq[2][TCH][DKH];
    __shared__ float sk[2][TCH][DKH];
    __shared__ float sv[2][TCH][DKH];

    const size_t rowbase = (size_t)(b * SEQ) * DMODEL + h * DKH;
    const int bbase = b * SEQ * HEADS + h;

    const unsigned sqa = (unsigned)__cvta_generic_to_shared(sq);
    const unsigned ska = (unsigned)__cvta_generic_to_shared(sk);
    const unsigned sva = (unsigned)__cvta_generic_to_shared(sv);

    // per-chunk staging: 3 arrays x 32 rows x 8 x 16B = 768 cp16, 24 per lane
#define DELTA_ISSUE(C, S)                                                        \
    do {                                                                         \
        int _t0 = (C) * TCH;                                                     \
        _Pragma("unroll")                                                        \
        for (int _i = 0; _i < 24; _i++) {                                        \
            int _idx = lane + _i * 32;                                           \
            int _a   = _idx >> 8;                                                \
            int _row = (_idx >> 3) & 31;                                         \
            int _cc  = _idx & 7;                                                 \
            const float* _gp = (_a == 0) ? g_q : (_a == 1) ? g_k : g_v;          \
            unsigned _sb = (_a == 0) ? sqa : (_a == 1) ? ska : sva;              \
            cp_async16(_sb + ((unsigned)(S) * TCH * DKH + _row * DKH + _cc * 4) * 4, \
                       _gp + rowbase + (size_t)(_t0 + _row) * DMODEL + _cc * 4); \
        }                                                                        \
        asm volatile("cp.async.commit_group;\n" ::);                             \
    } while (0)

    const int NCH = SEQ / TCH;

    // prologue: chunk 0 + its beta
    float bcur = g_beta[bbase + lane * HEADS];
    DELTA_ISSUE(0, 0);

    for (int c = 0; c < NCH; c++) {
        const int s = c & 1;
        float bnext = 0.f;
        if (c + 1 < NCH) {
            bnext = g_beta[bbase + ((c + 1) * TCH + lane) * HEADS];
            DELTA_ISSUE(c + 1, s ^ 1);
            asm volatile("cp.async.wait_group 1;\n" ::);
        } else {
            asm volatile("cp.async.wait_group 0;\n" ::);
        }
        __syncwarp();

        const int t0 = c * TCH;
#pragma unroll 4
        for (int tt = 0; tt < TCH; tt++) {
            const float* kk = &sk[s][tt][0];
            const float* qq = &sq[s][tt][0];
            float vv = sv[s][tt][lane];
            float bt = __shfl_sync(0xffffffffu, bcur, tt);

            // pf/ps: packed dot over k-dim, 2 accumulators each
            ull k2[16];
            ull pf0 = 0ull, pf1 = 0ull, ps0 = 0ull, ps1 = 0ull;
#pragma unroll
            for (int j = 0; j < 16; j += 2) {
                k2[j]     = *(const ull*)&kk[2 * j];
                k2[j + 1] = *(const ull*)&kk[2 * j + 2];
                pf0 = fma2(k2[j],     Sf[j],     pf0);
                pf1 = fma2(k2[j + 1], Sf[j + 1], pf1);
                ps0 = fma2(k2[j],     Ss[j],     ps0);
                ps1 = fma2(k2[j + 1], Ss[j + 1], ps1);
            }
            float pa, pb;
            unpack2(add2(pf0, pf1), pa, pb);
            float pf = pa + pb;
            unpack2(add2(ps0, ps1), pa, pb);
            float ps = pa + pb;

            float cf = bt * (vv - pf);
            float cs = bt * (vv - ps);
            const ull cf2 = pack2(cf, cf);
            const ull cs2 = pack2(cs, cs);

            // state update + output accumulation
            ull of0 = 0ull, of1 = 0ull, os0 = 0ull, os1 = 0ull;
#pragma unroll
            for (int j = 0; j < 16; j += 2) {
                ull q2a = *(const ull*)&qq[2 * j];
                ull q2b = *(const ull*)&qq[2 * j + 2];
                Sf[j]     = fma2(gf2, Sf[j],     mul2(k2[j],     cf2));
                Sf[j + 1] = fma2(gf2, Sf[j + 1], mul2(k2[j + 1], cf2));
                Ss[j]     = fma2(gs2, Ss[j],     mul2(k2[j],     cs2));
                Ss[j + 1] = fma2(gs2, Ss[j + 1], mul2(k2[j + 1], cs2));
                of0 = fma2(q2a, Sf[j],     of0);
                of1 = fma2(q2b, Sf[j + 1], of1);
                os0 = fma2(q2a, Ss[j],     os0);
                os1 = fma2(q2b, Ss[j + 1], os1);
            }
            float oa, ob;
            unpack2(add2(add2(of0, of1), add2(os0, os1)), oa, ob);
            g_o[rowbase + (size_t)(t0 + tt) * DMODEL + lane] = 0.5f * (oa + ob);
        }
        __syncwarp();
        bcur = bnext;
    }
#undef DELTA_ISSUE
}

// ---------------- masked mean pool + l2 normalize ----------------
__global__ void pool_kernel(const float* __restrict__ mask, float* __restrict__ out) {
    int b = blockIdx.x;
    int d = threadIdx.x;        // 384 threads
    __shared__ float red[12];

    float s = 0.f, msum = 0.f;
    for (int l = 0; l < SEQ; l++) {
        float mv = mask[b * SEQ + l];
        s += g_x[(size_t)(b * SEQ + l) * DMODEL + d] * mv;
        msum += mv;
    }
    float emb = s / fmaxf(msum, 1e-9f);

    float ss = warpSum(emb * emb);
    if ((d & 31) == 0) red[d >> 5] = ss;
    __syncthreads();
    float tot = 0.f;
#pragma unroll
    for (int w = 0; w < 12; w++) tot += red[w];
    float n = fmaxf(sqrtf(tot), 1e-12f);
    out[b * DMODEL + d] = emb / n;
}

// ---------------- launch ----------------
extern "C" void kernel_launch(void* const* d_in, const int* in_sizes, int n_in,
                              void* d_out, int out_size) {
    const int*   input_ids = (const int*)  d_in[0];
    const float* attn_mask = (const float*)d_in[1];
    const float* word_emb  = (const float*)d_in[2];
    const float* pos_emb   = (const float*)d_in[3];
    const float* type_emb  = (const float*)d_in[4];
    const float* emb_ln_g  = (const float*)d_in[5];
    const float* emb_ln_b  = (const float*)d_in[6];
    const float* Wq  = (const float*)d_in[7];
    const float* bq  = (const float*)d_in[8];
    const float* Wk  = (const float*)d_in[9];
    const float* bk  = (const float*)d_in[10];
    const float* Wv  = (const float*)d_in[11];
    const float* bv  = (const float*)d_in[12];
    const float* Wb  = (const float*)d_in[13];
    const float* dfa = (const float*)d_in[14];
    const float* dsl = (const float*)d_in[15];
    const float* Wo  = (const float*)d_in[16];
    const float* bo  = (const float*)d_in[17];
    const float* ln1g = (const float*)d_in[18];
    const float* ln1b = (const float*)d_in[19];
    const float* W1  = (const float*)d_in[20];
    const float* b1  = (const float*)d_in[21];
    const float* W2  = (const float*)d_in[22];
    const float* b2  = (const float*)d_in[23];
    const float* ln2g = (const float*)d_in[24];
    const float* ln2b = (const float*)d_in[25];
    float* out = (float*)d_out;

    float *px, *pq, *pk, *pv, *po, *pt, *ph;
    cudaGetSymbolAddress((void**)&px, g_x);
    cudaGetSymbolAddress((void**)&pq, g_q);
    cudaGetSymbolAddress((void**)&pk, g_k);
    cudaGetSymbolAddress((void**)&pv, g_v);
    cudaGetSymbolAddress((void**)&po, g_o);
    cudaGetSymbolAddress((void**)&pt, g_t);
    cudaGetSymbolAddress((void**)&ph, g_h);

    cudaFuncSetAttribute(tf32_gemm_async<0>,
                         cudaFuncAttributeMaxDynamicSharedMemorySize, GEMM_SMEM);
    cudaFuncSetAttribute(tf32_gemm_async<1>,
                         cudaFuncAttributeMaxDynamicSharedMemorySize, GEMM_SMEM);
    cudaFuncSetAttribute(tf32_gemm_qkv,
                         cudaFuncAttributeMaxDynamicSharedMemorySize, GEMM_SMEM);

    embed_ln_kernel<<<NTOK, 128>>>(input_ids, word_emb, pos_emb, type_emb, emb_ln_g, emb_ln_b);

    dim3 gProj(DMODEL / 128, NTOK / 128);       // (3,256)
    dim3 gQKV(DMODEL / 128, NTOK / 128, 3);     // (3,256,3)
    dim3 gFF1(DFF / 128, NTOK / 128);           // (12,256)

    for (int i = 0; i < NLAYER; i++) {
        const float* Wqi = Wq + (size_t)i * DMODEL * DMODEL;
        const float* Wki = Wk + (size_t)i * DMODEL * DMODEL;
        const float* Wvi = Wv + (size_t)i * DMODEL * DMODEL;
        const float* Woi = Wo + (size_t)i * DMODEL * DMODEL;
        const float* W1i = W1 + (size_t)i * DMODEL * DFF;
        const float* W2i = W2 + (size_t)i * DFF * DMODEL;

        tf32_gemm_qkv<<<gQKV, 256, GEMM_SMEM>>>(
            px, Wqi, Wki, Wvi,
            bq + i * DMODEL, bk + i * DMODEL, bv + i * DMODEL,
            pq, pk, pv, attn_mask, NTOK, DMODEL, DMODEL);
        beta_kernel<<<NTOK, 384>>>(px, Wb + (size_t)i * DMODEL * HEADS, attn_mask);

        delta_kernel<<<BATCH * HEADS, 32>>>(dfa, dsl, i);

        tf32_gemm_async<0><<<gProj, 256, GEMM_SMEM>>>(po, Woi, bo + i * DMODEL, pt, NTOK, DMODEL, DMODEL);
        add_ln_kernel<<<NTOK, 128>>>(px, pt, ln1g + i * DMODEL, ln1b + i * DMODEL);

        tf32_gemm_async<1><<<gFF1, 256, GEMM_SMEM>>>(px, W1i, b1 + i * DFF, ph, NTOK, DFF, DMODEL);
        tf32_gemm_async<0><<<gProj, 256, GEMM_SMEM>>>(ph, W2i, b2 + i * DMODEL, pt, NTOK, DMODEL, DFF);
        add_ln_kernel<<<NTOK, 128>>>(px, pt, ln2g + i * DMODEL, ln2b + i * DMODEL);
    }

    pool_kernel<<<BATCH, 384>>>(attn_mask, out);
}

// round 14
// speedup vs baseline: 1.4647x; 1.4154x over previous
#include <cuda_runtime.h>
#include <cuda_fp16.h>
#include <math.h>

#define NLAYER 6
#define HEADS  12
#define DMODEL 384
#define DKH    32
#define DFF    1536
#define SEQ    512
#define BATCH  64
#define NTOK   (BATCH*SEQ)   /* 32768 */

typedef unsigned long long ull;

// ---------------- scratch (device globals; no allocs allowed) ----------------
__device__ float g_x[NTOK*DMODEL];
__device__ float g_q[NTOK*DMODEL];
__device__ float g_k[NTOK*DMODEL];
__device__ float g_v[NTOK*DMODEL];
__device__ float g_t[NTOK*DMODEL];
__device__ float g_beta[NTOK*HEADS];

// fp16 shadow activations (GEMM inputs) + fp16 weights
__device__ __align__(256) __half h_x[NTOK*DMODEL];
__device__ __align__(256) __half h_o[NTOK*DMODEL];
__device__ __align__(256) __half h_h[NTOK*DFF];
__device__ __align__(256) __half h_wq[NLAYER*DMODEL*DMODEL];
__device__ __align__(256) __half h_wk[NLAYER*DMODEL*DMODEL];
__device__ __align__(256) __half h_wv[NLAYER*DMODEL*DMODEL];
__device__ __align__(256) __half h_wo[NLAYER*DMODEL*DMODEL];
__device__ __align__(256) __half h_w1[NLAYER*DMODEL*DFF];
__device__ __align__(256) __half h_w2[NLAYER*DFF*DMODEL];

// ---------------- helpers ----------------
__device__ __forceinline__ float warpSum(float v) {
#pragma unroll
    for (int o = 16; o > 0; o >>= 1) v += __shfl_xor_sync(0xffffffffu, v, o);
    return v;
}

__device__ __forceinline__ float gelu_t(float x) {
    float u = 0.7978845608028654f * (x + 0.044715f * x * x * x);
    return 0.5f * x * (1.0f + tanhf(u));
}

__device__ __forceinline__ float sigm(float x) {
    return 1.0f / (1.0f + expf(-x));
}

// ---- packed f32x2 (Blackwell FFMA2 — only reachable via PTX) ----
__device__ __forceinline__ ull pack2(float lo, float hi) {
    ull r; asm("mov.b64 %0, {%1, %2};" : "=l"(r) : "f"(lo), "f"(hi)); return r;
}
__device__ __forceinline__ void unpack2(ull v, float& lo, float& hi) {
    asm("mov.b64 {%0, %1}, %2;" : "=f"(lo), "=f"(hi) : "l"(v));
}
__device__ __forceinline__ ull fma2(ull a, ull b, ull c) {
    ull d; asm("fma.rn.f32x2 %0, %1, %2, %3;" : "=l"(d) : "l"(a), "l"(b), "l"(c)); return d;
}
__device__ __forceinline__ ull mul2(ull a, ull b) {
    ull d; asm("mul.rn.f32x2 %0, %1, %2;" : "=l"(d) : "l"(a), "l"(b)); return d;
}
__device__ __forceinline__ ull add2(ull a, ull b) {
    ull d; asm("add.rn.f32x2 %0, %1, %2;" : "=l"(d) : "l"(a), "l"(b)); return d;
}

__device__ __forceinline__ void mma_f16(float* d, const unsigned* a, const unsigned* b) {
    asm volatile(
        "mma.sync.aligned.m16n8k16.row.col.f32.f16.f16.f32 "
        "{%0,%1,%2,%3}, {%4,%5,%6,%7}, {%8,%9}, {%0,%1,%2,%3};\n"
        : "+f"(d[0]), "+f"(d[1]), "+f"(d[2]), "+f"(d[3])
        : "r"(a[0]), "r"(a[1]), "r"(a[2]), "r"(a[3]),
          "r"(b[0]), "r"(b[1]));
}

__device__ __forceinline__ void ldsm_x4(unsigned* r, unsigned addr) {
    asm volatile("ldmatrix.sync.aligned.m8n8.x4.shared.b16 {%0,%1,%2,%3}, [%4];\n"
        : "=r"(r[0]), "=r"(r[1]), "=r"(r[2]), "=r"(r[3]) : "r"(addr));
}

__device__ __forceinline__ void ldsm_x4_t(unsigned* r, unsigned addr) {
    asm volatile("ldmatrix.sync.aligned.m8n8.x4.trans.shared.b16 {%0,%1,%2,%3}, [%4];\n"
        : "=r"(r[0]), "=r"(r[1]), "=r"(r[2]), "=r"(r[3]) : "r"(addr));
}

__device__ __forceinline__ void cp_async16(unsigned smem_addr, const void* gptr) {
    asm volatile("cp.async.cg.shared.global [%0], [%1], 16;\n"
        :: "r"(smem_addr), "l"(gptr));
}

// ---------------- fp32 -> fp16 conversion (grid-exact, n % 1024 == 0) -------
__global__ void f2h_kernel(const float* __restrict__ s, __half* __restrict__ d) {
    int i = (blockIdx.x * blockDim.x + threadIdx.x) * 4;
    float4 v = *(const float4*)(s + i);
    *(__half2*)(d + i)     = __floats2half2_rn(v.x, v.y);
    *(__half2*)(d + i + 2) = __floats2half2_rn(v.z, v.w);
}

// ---------------- embedding + layernorm ----------------
__global__ void embed_ln_kernel(const int* __restrict__ ids,
                                const float* __restrict__ we,
                                const float* __restrict__ pe,
                                const float* __restrict__ te,
                                const float* __restrict__ g,
                                const float* __restrict__ bta,
                                __half* __restrict__ hx) {
    int token = blockIdx.x;
    int l = token & (SEQ - 1);
    int id = ids[token];
    int tid = threadIdx.x;
    __shared__ float red[4];

    float v[3];
    float s = 0.f;
#pragma unroll
    for (int j = 0; j < 3; j++) {
        int d = tid + j * 128;
        float val = we[id * DMODEL + d] + pe[l * DMODEL + d] + te[d];
        v[j] = val; s += val;
    }
    s = warpSum(s);
    if ((tid & 31) == 0) red[tid >> 5] = s;
    __syncthreads();
    float mean = (red[0] + red[1] + red[2] + red[3]) * (1.0f / DMODEL);
    float s2 = 0.f;
#pragma unroll
    for (int j = 0; j < 3; j++) { float d0 = v[j] - mean; s2 += d0 * d0; }
    s2 = warpSum(s2);
    __syncthreads();
    if ((tid & 31) == 0) red[tid >> 5] = s2;
    __syncthreads();
    float var = (red[0] + red[1] + red[2] + red[3]) * (1.0f / DMODEL);
    float inv = rsqrtf(var + 1e-12f);
#pragma unroll
    for (int j = 0; j < 3; j++) {
        int d = tid + j * 128;
        float o = (v[j] - mean) * inv * g[d] + bta[d];
        g_x[token * DMODEL + d] = o;
        hx[token * DMODEL + d] = __float2half(o);
    }
}

// ---------------- residual add + layernorm (in-place on x, + fp16 shadow) ---
__global__ void add_ln_kernel(float* __restrict__ x,
                              const float* __restrict__ t,
                              __half* __restrict__ hx,
                              const float* __restrict__ g,
                              const float* __restrict__ bta) {
    int token = blockIdx.x;
    int tid = threadIdx.x;
    __shared__ float red[4];
    float v[3];
    float s = 0.f;
#pragma unroll
    for (int j = 0; j < 3; j++) {
        int d = tid + j * 128;
        float val = x[token * DMODEL + d] + t[token * DMODEL + d];
        v[j] = val; s += val;
    }
    s = warpSum(s);
    if ((tid & 31) == 0) red[tid >> 5] = s;
    __syncthreads();
    float mean = (red[0] + red[1] + red[2] + red[3]) * (1.0f / DMODEL);
    float s2 = 0.f;
#pragma unroll
    for (int j = 0; j < 3; j++) { float d0 = v[j] - mean; s2 += d0 * d0; }
    s2 = warpSum(s2);
    __syncthreads();
    if ((tid & 31) == 0) red[tid >> 5] = s2;
    __syncthreads();
    float var = (red[0] + red[1] + red[2] + red[3]) * (1.0f / DMODEL);
    float inv = rsqrtf(var + 1e-12f);
#pragma unroll
    for (int j = 0; j < 3; j++) {
        int d = tid + j * 128;
        float o = (v[j] - mean) * inv * g[d] + bta[d];
        x[token * DMODEL + d] = o;
        hx[token * DMODEL + d] = __float2half(o);
    }
}

// ---------------- FP16 tensor-core GEMM core (cp.async 4-stage, ldmatrix A+B)
// BM=128 BN=128 BK=16, 256 threads (8 warps 2x4), warp tile 64x32,
// m16n8k16 fp16 MMA with fp32 accumulate.
#define HSTAGES 4
#define HAPITCH 24    /* halves: 48B row pitch, conflict-free ldsm */
#define HBPITCH 136   /* halves: 272B row pitch, conflict-free ldsm */
#define HGEMM_SMEM (HSTAGES * (128 * HAPITCH + 16 * HBPITCH) * 2)

__device__ __forceinline__ void hgemm_core(
        const __half* __restrict__ A, const __half* __restrict__ B,
        int bm, int bn, int N, int K, __half* smem, float acc[4][4][4]) {
    __half* As = smem;                              // [S][128][HAPITCH]
    __half* Bs = smem + HSTAGES * 128 * HAPITCH;    // [S][16][HBPITCH]

    const int tid  = threadIdx.x;
    const int lane = tid & 31;
    const int wid  = tid >> 5;
    const int wm   = (wid & 1) * 64;
    const int wn   = (wid >> 1) * 32;

    const int a_row = tid >> 1;            // 0..127
    const int a_c   = (tid & 1) * 8;       // halves
    const int b_row = tid >> 4;            // 0..15
    const int b_c   = (tid & 15) * 8;      // halves

    const unsigned aSh = (unsigned)__cvta_generic_to_shared(As);
    const unsigned bSh = (unsigned)__cvta_generic_to_shared(Bs);

    const int arow = lane & 15;            // ldsm row-in-fragment
    const int aoff = (lane >> 4) * 8;      // ldsm col quadrant (halves)

    const int nk = K / 16;

#define ISSUE_H(KT, S)                                                          \
    do {                                                                        \
        int _k0 = (KT) * 16;                                                    \
        unsigned _ab = aSh + (unsigned)(S) * 128 * HAPITCH * 2;                 \
        unsigned _bb = bSh + (unsigned)(S) * 16 * HBPITCH * 2;                  \
        cp_async16(_ab + (a_row * HAPITCH + a_c) * 2,                           \
                   A + (size_t)(bm + a_row) * K + _k0 + a_c);                   \
        cp_async16(_bb + (b_row * HBPITCH + b_c) * 2,                           \
                   B + (size_t)(_k0 + b_row) * N + bn + b_c);                   \
        asm volatile("cp.async.commit_group;\n" ::);                            \
    } while (0)

#pragma unroll
    for (int s = 0; s < HSTAGES - 1; s++)
        ISSUE_H(s, s);

    for (int kt = 0; kt < nk; kt++) {
        asm volatile("cp.async.wait_group %0;\n" :: "n"(HSTAGES - 2));
        __syncthreads();

        int knext = kt + HSTAGES - 1;
        if (knext < nk) ISSUE_H(knext, knext % HSTAGES);
        else asm volatile("cp.async.commit_group;\n" ::);

        const unsigned aBase = aSh + (unsigned)(kt % HSTAGES) * 128 * HAPITCH * 2;
        const unsigned bBase = bSh + (unsigned)(kt % HSTAGES) * 16 * HBPITCH * 2;

        unsigned a[4][4];
#pragma unroll
        for (int im = 0; im < 4; im++)
            ldsm_x4(a[im], aBase +
                    (unsigned)(((wm + im * 16 + arow) * HAPITCH + aoff) * 2));

        unsigned bb[4][2];
#pragma unroll
        for (int p = 0; p < 2; p++) {
            unsigned t4[4];
            ldsm_x4_t(t4, bBase +
                      (unsigned)(((lane & 15) * HBPITCH + wn + p * 16 + aoff) * 2));
            bb[2 * p][0] = t4[0]; bb[2 * p][1] = t4[1];
            bb[2 * p + 1][0] = t4[2]; bb[2 * p + 1][1] = t4[3];
        }

#pragma unroll
        for (int im = 0; im < 4; im++)
#pragma unroll
            for (int in_ = 0; in_ < 4; in_++)
                mma_f16(acc[im][in_], a[im], bb[in_]);
    }
#undef ISSUE_H
}

// ---------------- generic GEMM: EPI=0: fp32 out; EPI=1: fp16 out + double-gelu
template<int EPI>
__global__ void __launch_bounds__(256, 2) hgemm_kernel(
        const __half* __restrict__ A, const __half* __restrict__ B,
        const float* __restrict__ bias, void* __restrict__ Cv,
        int M, int N, int K) {
    extern __shared__ __half hsmem[];
    const int tid  = threadIdx.x;
    const int lane = tid & 31;
    const int wid  = tid >> 5;
    const int tig  = lane & 3;
    const int grp  = lane >> 2;
    const int wm   = (wid & 1) * 64;
    const int wn   = (wid >> 1) * 32;
    const int bm   = blockIdx.y * 128;
    const int bn   = blockIdx.x * 128;

    float acc[4][4][4];
#pragma unroll
    for (int im = 0; im < 4; im++)
#pragma unroll
        for (int in_ = 0; in_ < 4; in_++)
#pragma unroll
            for (int r = 0; r < 4; r++) acc[im][in_][r] = 0.f;

    hgemm_core(A, B, bm, bn, N, K, hsmem, acc);

#pragma unroll
    for (int im = 0; im < 4; im++) {
        int row0 = bm + wm + im * 16 + grp;
#pragma unroll
        for (int in_ = 0; in_ < 4; in_++) {
            int col = bn + wn + in_ * 8 + 2 * tig;
            float b0 = bias[col], b1 = bias[col + 1];
            float v0 = acc[im][in_][0] + b0;
            float v1 = acc[im][in_][1] + b1;
            float v2 = acc[im][in_][2] + b0;
            float v3 = acc[im][in_][3] + b1;
            if (EPI == 1) {
                v0 = gelu_t(gelu_t(v0)); v1 = gelu_t(gelu_t(v1));
                v2 = gelu_t(gelu_t(v2)); v3 = gelu_t(gelu_t(v3));
                __half* C = (__half*)Cv;
                *(__half2*)&C[(size_t)row0 * N + col]       = __floats2half2_rn(v0, v1);
                *(__half2*)&C[(size_t)(row0 + 8) * N + col] = __floats2half2_rn(v2, v3);
            } else {
                float* C = (float*)Cv;
                *(float2*)&C[(size_t)row0 * N + col]       = make_float2(v0, v1);
                *(float2*)&C[(size_t)(row0 + 8) * N + col] = make_float2(v2, v3);
            }
        }
    }
}

// ---------------- fused QKV GEMM with per-head l2-norm epilogue --------------
// blockIdx.z: 0=Q (norm), 1=K (norm*mask), 2=V (plain). fp32 outputs for delta.
__global__ void __launch_bounds__(256, 2) hgemm_qkv(
        const __half* __restrict__ A,
        const __half* __restrict__ BQ, const __half* __restrict__ BK_,
        const __half* __restrict__ BV,
        const float* __restrict__ bqv, const float* __restrict__ bkv,
        const float* __restrict__ bvv,
        float* __restrict__ CQ, float* __restrict__ CK, float* __restrict__ CV,
        const float* __restrict__ mask, int M, int N, int K) {
    extern __shared__ __half hsmem[];
    const int z = blockIdx.z;
    const __half* B   = (z == 0) ? BQ  : (z == 1) ? BK_ : BV;
    const float* bias = (z == 0) ? bqv : (z == 1) ? bkv : bvv;
    float* C          = (z == 0) ? CQ  : (z == 1) ? CK  : CV;

    const int tid  = threadIdx.x;
    const int lane = tid & 31;
    const int wid  = tid >> 5;
    const int tig  = lane & 3;
    const int grp  = lane >> 2;
    const int wm   = (wid & 1) * 64;
    const int wn   = (wid >> 1) * 32;
    const int bm   = blockIdx.y * 128;
    const int bn   = blockIdx.x * 128;

    float acc[4][4][4];
#pragma unroll
    for (int im = 0; im < 4; im++)
#pragma unroll
        for (int in_ = 0; in_ < 4; in_++)
#pragma unroll
            for (int r = 0; r < 4; r++) acc[im][in_][r] = 0.f;

    hgemm_core(A, B, bm, bn, N, K, hsmem, acc);

#pragma unroll
    for (int im = 0; im < 4; im++) {
        int row0 = bm + wm + im * 16 + grp;
#pragma unroll
        for (int in_ = 0; in_ < 4; in_++) {
            int col = bn + wn + in_ * 8 + 2 * tig;
            float b0 = bias[col], b1 = bias[col + 1];
            acc[im][in_][0] += b0; acc[im][in_][1] += b1;
            acc[im][in_][2] += b0; acc[im][in_][3] += b1;
        }
        float sA = 1.f, sB = 1.f;
        if (z < 2) {
            float ssA = 0.f, ssB = 0.f;
#pragma unroll
            for (int in_ = 0; in_ < 4; in_++) {
                ssA += acc[im][in_][0] * acc[im][in_][0]
                     + acc[im][in_][1] * acc[im][in_][1];
                ssB += acc[im][in_][2] * acc[im][in_][2]
                     + acc[im][in_][3] * acc[im][in_][3];
            }
            ssA += __shfl_xor_sync(0xffffffffu, ssA, 1);
            ssA += __shfl_xor_sync(0xffffffffu, ssA, 2);
            ssB += __shfl_xor_sync(0xffffffffu, ssB, 1);
            ssB += __shfl_xor_sync(0xffffffffu, ssB, 2);
            sA = 1.0f / (sqrtf(ssA) + 1e-6f);
            sB = 1.0f / (sqrtf(ssB) + 1e-6f);
            if (z == 1) {
                sA *= mask[row0];
                sB *= mask[row0 + 8];
            }
        }
#pragma unroll
        for (int in_ = 0; in_ < 4; in_++) {
            int col = bn + wn + in_ * 8 + 2 * tig;
            *(float2*)&C[(size_t)row0 * N + col] =
                make_float2(acc[im][in_][0] * sA, acc[im][in_][1] * sA);
            *(float2*)&C[(size_t)(row0 + 8) * N + col] =
                make_float2(acc[im][in_][2] * sB, acc[im][in_][3] * sB);
        }
    }
}

// ---------------- beta = sigmoid(x @ Wb) * mask ----------------
__global__ void beta_kernel(const float* __restrict__ x, const float* __restrict__ Wb,
                            const float* __restrict__ mask) {
    int token = blockIdx.x;
    int h = threadIdx.x >> 5;
    int lane = threadIdx.x & 31;
    const float* xr = x + (size_t)token * DMODEL;
    float s = 0.f;
#pragma unroll
    for (int k = lane; k < DMODEL; k += 32) s += xr[k] * Wb[k * HEADS + h];
    s = warpSum(s);
    if (lane == 0) g_beta[token * HEADS + h] = sigm(s) * mask[token];
}

// ---------------- delta recurrence: one warp per (b,h), f32x2 math,
//                  chunked cp.async SMEM staging (double-buffered) ----------
#define TCH 32   /* timesteps per chunk; SEQ/TCH = 16 chunks */

__global__ void __launch_bounds__(32) delta_kernel(
        const float* __restrict__ decay_f,
        const float* __restrict__ decay_s,
        __half* __restrict__ ho,
        int layer) {
    int bh = blockIdx.x;
    int b = bh / HEADS;
    int h = bh % HEADS;
    int lane = threadIdx.x;

    float gf = sigm(decay_f[layer * HEADS + h]);
    float gs = sigm(decay_s[layer * HEADS + h]);
    const ull gf2 = pack2(gf, gf);
    const ull gs2 = pack2(gs, gs);

    ull Sf[16], Ss[16];
#pragma unroll
    for (int j = 0; j < 16; j++) { Sf[j] = 0ull; Ss[j] = 0ull; }

    __shared__ float sq[2][TCH][DKH];
    __shared__ float sk[2][TCH][DKH];
    __shared__ float sv[2][TCH][DKH];

    const size_t rowbase = (size_t)(b * SEQ) * DMODEL + h * DKH;
    const int bbase = b * SEQ * HEADS + h;

    const unsigned sqa = (unsigned)__cvta_generic_to_shared(sq);
    const unsigned ska = (unsigned)__cvta_generic_to_shared(sk);
    const unsigned sva = (unsigned)__cvta_generic_to_shared(sv);

#define DELTA_ISSUE(C, S)                                                        \
    do {                                                                         \
        int _t0 = (C) * TCH;                                                     \
        _Pragma("unroll")                                                        \
        for (int _i = 0; _i < 24; _i++) {                                        \
            int _idx = lane + _i * 32;                                           \
            int _a   = _idx >> 8;                                                \
            int _row = (_idx >> 3) & 31;                                         \
            int _cc  = _idx & 7;                                                 \
            const float* _gp = (_a == 0) ? g_q : (_a == 1) ? g_k : g_v;          \
            unsigned _sb = (_a == 0) ? sqa : (_a == 1) ? ska : sva;              \
            cp_async16(_sb + ((unsigned)(S) * TCH * DKH + _row * DKH + _cc * 4) * 4, \
                       _gp + rowbase + (size_t)(_t0 + _row) * DMODEL + _cc * 4); \
        }                                                                        \
        asm volatile("cp.async.commit_group;\n" ::);                             \
    } while (0)

    const int NCH = SEQ / TCH;

    float bcur = g_beta[bbase + lane * HEADS];
    DELTA_ISSUE(0, 0);

    for (int c = 0; c < NCH; c++) {
        const int s = c & 1;
        float bnext = 0.f;
        if (c + 1 < NCH) {
            bnext = g_beta[bbase + ((c + 1) * TCH + lane) * HEADS];
            DELTA_ISSUE(c + 1, s ^ 1);
            asm volatile("cp.async.wait_group 1;\n" ::);
        } else {
            asm volatile("cp.async.wait_group 0;\n" ::);
        }
        __syncwarp();

        const int t0 = c * TCH;
#pragma unroll 4
        for (int tt = 0; tt < TCH; tt++) {
            const float* kk = &sk[s][tt][0];
            const float* qq = &sq[s][tt][0];
            float vv = sv[s][tt][lane];
            float bt = __shfl_sync(0xffffffffu, bcur, tt);

            ull k2[16];
            ull pf0 = 0ull, pf1 = 0ull, ps0 = 0ull, ps1 = 0ull;
#pragma unroll
            for (int j = 0; j < 16; j += 2) {
                k2[j]     = *(const ull*)&kk[2 * j];
                k2[j + 1] = *(const ull*)&kk[2 * j + 2];
                pf0 = fma2(k2[j],     Sf[j],     pf0);
                pf1 = fma2(k2[j + 1], Sf[j + 1], pf1);
                ps0 = fma2(k2[j],     Ss[j],     ps0);
                ps1 = fma2(k2[j + 1], Ss[j + 1], ps1);
            }
            float pa, pb;
            unpack2(add2(pf0, pf1), pa, pb);
            float pf = pa + pb;
            unpack2(add2(ps0, ps1), pa, pb);
            float ps = pa + pb;

            float cf = bt * (vv - pf);
            float cs = bt * (vv - ps);
            const ull cf2 = pack2(cf, cf);
            const ull cs2 = pack2(cs, cs);

            ull of0 = 0ull, of1 = 0ull, os0 = 0ull, os1 = 0ull;
#pragma unroll
            for (int j = 0; j < 16; j += 2) {
                ull q2a = *(const ull*)&qq[2 * j];
                ull q2b = *(const ull*)&qq[2 * j + 2];
                Sf[j]     = fma2(gf2, Sf[j],     mul2(k2[j],     cf2));
                Sf[j + 1] = fma2(gf2, Sf[j + 1], mul2(k2[j + 1], cf2));
                Ss[j]     = fma2(gs2, Ss[j],     mul2(k2[j],     cs2));
                Ss[j + 1] = fma2(gs2, Ss[j + 1], mul2(k2[j + 1], cs2));
                of0 = fma2(q2a, Sf[j],     of0);
                of1 = fma2(q2b, Sf[j + 1], of1);
                os0 = fma2(q2a, Ss[j],     os0);
                os1 = fma2(q2b, Ss[j + 1], os1);
            }
            float oa, ob;
            unpack2(add2(add2(of0, of1), add2(os0, os1)), oa, ob);
            ho[rowbase + (size_t)(t0 + tt) * DMODEL + lane] =
                __float2half(0.5f * (oa + ob));
        }
        __syncwarp();
        bcur = bnext;
    }
#undef DELTA_ISSUE
}

// ---------------- masked mean pool + l2 normalize ----------------
__global__ void pool_kernel(const float* __restrict__ mask, float* __restrict__ out) {
    int b = blockIdx.x;
    int d = threadIdx.x;        // 384 threads
    __shared__ float red[12];

    float s = 0.f, msum = 0.f;
    for (int l = 0; l < SEQ; l++) {
        float mv = mask[b * SEQ + l];
        s += g_x[(size_t)(b * SEQ + l) * DMODEL + d] * mv;
        msum += mv;
    }
    float emb = s / fmaxf(msum, 1e-9f);

    float ss = warpSum(emb * emb);
    if ((d & 31) == 0) red[d >> 5] = ss;
    __syncthreads();
    float tot = 0.f;
#pragma unroll
    for (int w = 0; w < 12; w++) tot += red[w];
    float n = fmaxf(sqrtf(tot), 1e-12f);
    out[b * DMODEL + d] = emb / n;
}

// ---------------- launch ----------------
extern "C" void kernel_launch(void* const* d_in, const int* in_sizes, int n_in,
                              void* d_out, int out_size) {
    const int*   input_ids = (const int*)  d_in[0];
    const float* attn_mask = (const float*)d_in[1];
    const float* word_emb  = (const float*)d_in[2];
    const float* pos_emb   = (const float*)d_in[3];
    const float* type_emb  = (const float*)d_in[4];
    const float* emb_ln_g  = (const float*)d_in[5];
    const float* emb_ln_b  = (const float*)d_in[6];
    const float* Wq  = (const float*)d_in[7];
    const float* bq  = (const float*)d_in[8];
    const float* Wk  = (const float*)d_in[9];
    const float* bk  = (const float*)d_in[10];
    const float* Wv  = (const float*)d_in[11];
    const float* bv  = (const float*)d_in[12];
    const float* Wb  = (const float*)d_in[13];
    const float* dfa = (const float*)d_in[14];
    const float* dsl = (const float*)d_in[15];
    const float* Wo  = (const float*)d_in[16];
    const float* bo  = (const float*)d_in[17];
    const float* ln1g = (const float*)d_in[18];
    const float* ln1b = (const float*)d_in[19];
    const float* W1  = (const float*)d_in[20];
    const float* b1  = (const float*)d_in[21];
    const float* W2  = (const float*)d_in[22];
    const float* b2  = (const float*)d_in[23];
    const float* ln2g = (const float*)d_in[24];
    const float* ln2b = (const float*)d_in[25];
    float* out = (float*)d_out;

    float *px, *pq, *pk, *pv, *pt;
    cudaGetSymbolAddress((void**)&px, g_x);
    cudaGetSymbolAddress((void**)&pq, g_q);
    cudaGetSymbolAddress((void**)&pk, g_k);
    cudaGetSymbolAddress((void**)&pv, g_v);
    cudaGetSymbolAddress((void**)&pt, g_t);

    __half *phx, *pho, *phh, *pwq, *pwk, *pwv, *pwo, *pw1, *pw2;
    cudaGetSymbolAddress((void**)&phx, h_x);
    cudaGetSymbolAddress((void**)&pho, h_o);
    cudaGetSymbolAddress((void**)&phh, h_h);
    cudaGetSymbolAddress((void**)&pwq, h_wq);
    cudaGetSymbolAddress((void**)&pwk, h_wk);
    cudaGetSymbolAddress((void**)&pwv, h_wv);
    cudaGetSymbolAddress((void**)&pwo, h_wo);
    cudaGetSymbolAddress((void**)&pw1, h_w1);
    cudaGetSymbolAddress((void**)&pw2, h_w2);

    cudaFuncSetAttribute(hgemm_kernel<0>,
                         cudaFuncAttributeMaxDynamicSharedMemorySize, HGEMM_SMEM);
    cudaFuncSetAttribute(hgemm_kernel<1>,
                         cudaFuncAttributeMaxDynamicSharedMemorySize, HGEMM_SMEM);
    cudaFuncSetAttribute(hgemm_qkv,
                         cudaFuncAttributeMaxDynamicSharedMemorySize, HGEMM_SMEM);

    // weight conversion (grid-exact: all sizes divisible by 1024)
    const int NDD = NLAYER * DMODEL * DMODEL;
    const int NDF = NLAYER * DMODEL * DFF;
    f2h_kernel<<<NDD / 1024, 256>>>(Wq, pwq);
    f2h_kernel<<<NDD / 1024, 256>>>(Wk, pwk);
    f2h_kernel<<<NDD / 1024, 256>>>(Wv, pwv);
    f2h_kernel<<<NDD / 1024, 256>>>(Wo, pwo);
    f2h_kernel<<<NDF / 1024, 256>>>(W1, pw1);
    f2h_kernel<<<NDF / 1024, 256>>>(W2, pw2);

    embed_ln_kernel<<<NTOK, 128>>>(input_ids, word_emb, pos_emb, type_emb,
                                   emb_ln_g, emb_ln_b, phx);

    dim3 gProj(DMODEL / 128, NTOK / 128);       // (3,256)
    dim3 gQKV(DMODEL / 128, NTOK / 128, 3);     // (3,256,3)
    dim3 gFF1(DFF / 128, NTOK / 128);           // (12,256)

    for (int i = 0; i < NLAYER; i++) {
        const __half* hWqi = pwq + (size_t)i * DMODEL * DMODEL;
        const __half* hWki = pwk + (size_t)i * DMODEL * DMODEL;
        const __half* hWvi = pwv + (size_t)i * DMODEL * DMODEL;
        const __half* hWoi = pwo + (size_t)i * DMODEL * DMODEL;
        const __half* hW1i = pw1 + (size_t)i * DMODEL * DFF;
        const __half* hW2i = pw2 + (size_t)i * DFF * DMODEL;

        hgemm_qkv<<<gQKV, 256, HGEMM_SMEM>>>(
            phx, hWqi, hWki, hWvi,
            bq + i * DMODEL, bk + i * DMODEL, bv + i * DMODEL,
            pq, pk, pv, attn_mask, NTOK, DMODEL, DMODEL);
        beta_kernel<<<NTOK, 384>>>(px, Wb + (size_t)i * DMODEL * HEADS, attn_mask);

        delta_kernel<<<BATCH * HEADS, 32>>>(dfa, dsl, pho, i);

        hgemm_kernel<0><<<gProj, 256, HGEMM_SMEM>>>(
            pho, hWoi, bo + i * DMODEL, pt, NTOK, DMODEL, DMODEL);
        add_ln_kernel<<<NTOK, 128>>>(px, pt, phx, ln1g + i * DMODEL, ln1b + i * DMODEL);

        hgemm_kernel<1><<<gFF1, 256, HGEMM_SMEM>>>(
            phx, hW1i, b1 + i * DFF, phh, NTOK, DFF, DMODEL);
        hgemm_kernel<0><<<gProj, 256, HGEMM_SMEM>>>(
            phh, hW2i, b2 + i * DMODEL, pt, NTOK, DMODEL, DFF);
        add_ln_kernel<<<NTOK, 128>>>(px, pt, phx, ln2g + i * DMODEL, ln2b + i * DMODEL);
    }

    pool_kernel<<<BATCH, 384>>>(attn_mask, out);
}